// round 15
// baseline (speedup 1.0000x reference)
#include <cuda_runtime.h>
#include <cuda_bf16.h>
#include <cstdint>

// Problem constants
#define TSTEPS 512
#define BB 64
#define II 128
#define HH 512
#define OO 128
#define KK 32
#define ZK 640                  // I + H
#define NBLK 136                // 128 gate blocks (12 cols) + 8 out blocks (16 cols)
#define CLUSTER 4
#define NTH 256
#define GT (NBLK*NTH)

// smem layout (bytes)
#define HSM_OFF   0             // h slice [512][64] f32 = 131072
#define XSM_OFF   131072        // gate: x slice [128][64] f32 = 32768
#define WSO_OFF   131072        // out: weights k-paired [256][16] ull = 32768 (overlaps xsm)
#define WSG_OFF   163840        // gate weights k-paired [320][12] ull = 30720
#define WD_OFF    194560        // frac-diff weights [4][32] f32 = 512
#define MBAR_OFF  195072        // 4 h mbars + 1 x mbar (8B each)
#define SMEM_BYTES (MBAR_OFF + 64)

typedef unsigned long long ull;

// ------------- static device scratch (no allocations) -------------
__device__ float g_xT[TSTEPS*II*BB];     // inputs transposed: [t][k][b]
__device__ float g_zH[HH*BB];            // h_{t-1}: [h][b]
__device__ float g_ring[KK*HH*BB];       // last 32 cell states: [j][h][b]
__device__ unsigned g_cnt;
__device__ volatile unsigned g_sense_v;

// ------------- helpers -------------
__device__ __forceinline__ ull ffma2(ull a, ull b, ull c) {
    ull d;
    asm("fma.rn.f32x2 %0, %1, %2, %3;" : "=l"(d) : "l"(a), "l"(b), "l"(c));
    return d;
}
__device__ __forceinline__ ull pack2(float lo, float hi) {
    ull r;
    asm("mov.b64 %0, {%1, %2};" : "=l"(r) : "f"(lo), "f"(hi));
    return r;
}
__device__ __forceinline__ float lo32(ull v) { return __uint_as_float((unsigned)v); }
__device__ __forceinline__ float hi32(ull v) { return __uint_as_float((unsigned)(v >> 32)); }
__device__ __forceinline__ float sigm(float x) { return 1.f / (1.f + __expf(-x)); }

__device__ __forceinline__ unsigned smem_u32(const void* p) {
    return (unsigned)__cvta_generic_to_shared(p);
}
__device__ __forceinline__ void mbar_init(unsigned mbar, unsigned cnt) {
    asm volatile("mbarrier.init.shared.b64 [%0], %1;" :: "r"(mbar), "r"(cnt) : "memory");
}
__device__ __forceinline__ void mbar_expect(unsigned mbar, unsigned bytes) {
    asm volatile("mbarrier.arrive.expect_tx.shared.b64 _, [%0], %1;"
                 :: "r"(mbar), "r"(bytes) : "memory");
}
__device__ __forceinline__ void bulk_g2s_mc(unsigned dst, const void* src,
                                            unsigned bytes, unsigned mbar,
                                            unsigned short mask) {
    asm volatile("cp.async.bulk.shared::cluster.global.mbarrier::complete_tx::bytes"
                 ".multicast::cluster [%0], [%1], %2, [%3], %4;"
                 :: "r"(dst), "l"(src), "r"(bytes), "r"(mbar), "h"(mask) : "memory");
}
__device__ __forceinline__ void mbar_wait(unsigned mbar, unsigned parity) {
    asm volatile(
        "{\n\t"
        ".reg .pred P;\n\t"
        "WAIT_%=:\n\t"
        "mbarrier.try_wait.parity.acquire.cta.shared::cta.b64 P, [%0], %1, 0x989680;\n\t"
        "@P bra.uni DONE_%=;\n\t"
        "bra.uni WAIT_%=;\n\t"
        "DONE_%=:\n\t"
        "}" :: "r"(mbar), "r"(parity) : "memory");
}

// Champion serial sense-reversing grid barrier; arrival pipelines at the LTS
// atomic ALU (~0.85 cyc/op single-address) so this is ~700 cyc total.
// State self-restores (even call count) for graph replay.
__device__ __forceinline__ void gridbar(unsigned n) {
    __threadfence();
    __syncthreads();
    if (threadIdx.x == 0) {
        unsigned s = (~n) & 1u;
        if (atomicAdd(&g_cnt, 1u) == NBLK - 1) {
            g_cnt = 0;
            __threadfence();
            g_sense_v = s;
        } else {
            while (g_sense_v != s) __nanosleep(16);
        }
    }
    __syncthreads();
}

extern __shared__ char smem_raw[];

__global__ void __launch_bounds__(NTH, 1) __cluster_dims__(CLUSTER, 1, 1)
mlstm_kernel(const float* __restrict__ inputs,
             const float* __restrict__ W_i, const float* __restrict__ b_i,
             const float* __restrict__ W_o, const float* __restrict__ b_o,
             const float* __restrict__ W_c, const float* __restrict__ b_c,
             const float* __restrict__ W_out, const float* __restrict__ b_out,
             const float* __restrict__ d_values,
             float* __restrict__ out)
{
    float* hsm   = (float*)(smem_raw + HSM_OFF);    // [512][64]
    float* xsm   = (float*)(smem_raw + XSM_OFF);    // [128][64] (gate only)
    ull*   wsg   = (ull*)(smem_raw + WSG_OFF);      // gate [320 kpairs][12]
    ull*   wso   = (ull*)(smem_raw + WSO_OFF);      // out  [256 kpairs][16]
    float* wd_sm = (float*)(smem_raw + WD_OFF);     // [4][32]
    ull*   redsm = (ull*)(smem_raw + HSM_OFF);      // reuse h region

    const unsigned hbar0 = smem_u32(smem_raw + MBAR_OFF);  // 4 mbars, 8B apart
    const unsigned xbar  = hbar0 + 32;

    const int tid  = threadIdx.x;
    const int blk  = blockIdx.x;
    const int gtid = blk * NTH + tid;
    const int lane = tid & 31;
    const int wid  = tid >> 5;
    const int rank = blk & (CLUSTER - 1);

    const bool isOut = (blk >= 128);
    const int h0  = blk * 4;                 // gate blocks: 4 h each
    const int oc0 = (blk - 128) * 16;        // out blocks: 16 cols each
    const int eh  = tid >> 6;                // elementwise hh (0..3)
    const int eb  = tid & 63;                // elementwise b

    // ---------------- init ----------------
    if (tid == 0) {
        for (int c = 0; c < 4; ++c) mbar_init(hbar0 + c * 8, 1);
        mbar_init(xbar, 1);
    }
    if (!isOut) {
        // gate weights k-PAIRED: warp w, p = kp - w*40: p<32 -> h rows
        // k0 = 128 + w*64 + 2p ; p>=32 -> x rows k0 = w*16 + 2*(p-32).
        for (int idx = tid; idx < 320 * 12; idx += NTH) {
            int kp = idx / 12;
            int j  = idx - kp * 12;
            int w  = kp / 40, p = kp - w * 40;
            int k0 = (p < 32) ? (128 + w * 64 + 2 * p) : (w * 16 + 2 * (p - 32));
            int hh = j / 3, g = j - hh * 3;
            const float* W = (g == 0) ? W_i : (g == 1) ? W_o : W_c;
            wsg[idx] = pack2(W[k0 * HH + h0 + hh], W[(k0 + 1) * HH + h0 + hh]);
        }
        if (tid < 4) {
            float dv = 0.5f * sigm(d_values[h0 + tid]);
            float v = 1.f;
            for (int i = 0; i < KK; ++i) {
                v = v * ((float)i - dv) / ((float)i + 1.f);
                wd_sm[tid * KK + (KK - 1 - i)] = v;
            }
        }
    } else {
        // out weights k-PAIRED: warp w owns pairs p in [0,32): h row k0 = w*64+2p.
        for (int idx = tid; idx < 256 * 16; idx += NTH) {
            int kp = idx >> 4;
            int j  = idx & 15;
            int w  = kp >> 5, p = kp & 31;
            int k0 = w * 64 + 2 * p;
            wso[idx] = pack2(W_out[k0 * OO + oc0 + j], W_out[(k0 + 1) * OO + oc0 + j]);
        }
    }
    float rbi = 0.f, rbo = 0.f, rbc = 0.f;
    if (!isOut) { rbi = b_i[h0 + eh]; rbo = b_o[h0 + eh]; rbc = b_c[h0 + eh]; }

    // Transpose inputs once: g_xT[t][k][b]
    for (int idx = gtid; idx < TSTEPS * II * BB; idx += GT) {
        int t = idx >> 13;
        int r = idx & 8191;
        int k = r & 127, b = r >> 7;
        g_xT[(size_t)t * 8192 + k * 64 + b] = inputs[((size_t)t * BB + b) * II + k];
    }
    for (int idx = gtid; idx < HH * BB; idx += GT) g_zH[idx] = 0.f;
    for (int idx = gtid; idx < KK * HH * BB; idx += GT) g_ring[idx] = 0.f;
    __syncthreads();
    unsigned barid = 0;
    gridbar(barid++);

    // Prefetch x(0): 4-way cooperative multicast slices (gate clusters only;
    // blocks 0..127 form 32 all-gate clusters, 128..135 two all-out clusters)
    if (!isOut && tid == 0) {
        mbar_expect(xbar, 32768);
        bulk_g2s_mc(smem_u32(xsm) + rank * 8192, g_xT + rank * 2048, 8192, xbar, 0xF);
    }

    unsigned hph = 0, xph = 0;
    float rv[KK];                 // register shift-ring: rv[j] = c_{u-32+j}
    #pragma unroll
    for (int j = 0; j < KK; ++j) rv[j] = 0.f;

    // ---------------- main scan ----------------
    for (int u = 0; u <= TSTEPS; ++u) {
        const bool active = isOut ? (u >= 1) : (u < TSTEPS);

        // h broadcast: each CTA loads ONLY its rank's 32KB slice and multicasts
        // it cluster-wide (4x less L2 traffic). mbar c receives rank-c's slice.
        if (active && tid == 0) {
            #pragma unroll
            for (int c = 0; c < 4; ++c) mbar_expect(hbar0 + c * 8, 32768);
            bulk_g2s_mc(smem_u32(hsm) + rank * 32768, g_zH + rank * 8192,
                        32768, hbar0 + rank * 8, 0xF);
        }

        if (active) {
            if (!isOut) {
                ull accA[12], accB[12];   // accA: b=lane, accB: b=lane+32
                #pragma unroll
                for (int j = 0; j < 12; ++j) { accA[j] = 0ULL; accB[j] = 0ULL; }
                // x part first: 8 k-pairs, prefetched last step.
                mbar_wait(xbar, xph);
                {
                    const float* zr = xsm + (wid * 16) * 64 + lane;
                    const ulonglong2* wp = (const ulonglong2*)(wsg + (size_t)(wid * 40 + 32) * 12);
                    #pragma unroll
                    for (int p = 0; p < 8; ++p) {
                        ull zA = pack2(zr[(2*p)*64],      zr[(2*p+1)*64]);
                        ull zB = pack2(zr[(2*p)*64 + 32], zr[(2*p+1)*64 + 32]);
                        ulonglong2 w0 = wp[p*6+0], w1 = wp[p*6+1], w2 = wp[p*6+2];
                        accA[0] = ffma2(zA, w0.x, accA[0]);  accB[0] = ffma2(zB, w0.x, accB[0]);
                        accA[1] = ffma2(zA, w0.y, accA[1]);  accB[1] = ffma2(zB, w0.y, accB[1]);
                        accA[2] = ffma2(zA, w1.x, accA[2]);  accB[2] = ffma2(zB, w1.x, accB[2]);
                        accA[3] = ffma2(zA, w1.y, accA[3]);  accB[3] = ffma2(zB, w1.y, accB[3]);
                        accA[4] = ffma2(zA, w2.x, accA[4]);  accB[4] = ffma2(zB, w2.x, accB[4]);
                        accA[5] = ffma2(zA, w2.y, accA[5]);  accB[5] = ffma2(zB, w2.y, accB[5]);
                        ulonglong2 w3 = wp[p*6+3], w4 = wp[p*6+4], w5 = wp[p*6+5];
                        accA[6] = ffma2(zA, w3.x, accA[6]);   accB[6]  = ffma2(zB, w3.x, accB[6]);
                        accA[7] = ffma2(zA, w3.y, accA[7]);   accB[7]  = ffma2(zB, w3.y, accB[7]);
                        accA[8] = ffma2(zA, w4.x, accA[8]);   accB[8]  = ffma2(zB, w4.x, accB[8]);
                        accA[9] = ffma2(zA, w4.y, accA[9]);   accB[9]  = ffma2(zB, w4.y, accB[9]);
                        accA[10] = ffma2(zA, w5.x, accA[10]); accB[10] = ffma2(zB, w5.x, accB[10]);
                        accA[11] = ffma2(zA, w5.y, accA[11]); accB[11] = ffma2(zB, w5.y, accB[11]);
                    }
                }
                // h part: 32 k-pairs; wait only this warp-pair's slice.
                mbar_wait(hbar0 + (wid >> 1) * 8, hph);
                {
                    const float* zr = hsm + (wid * 64) * 64 + lane;
                    const ulonglong2* wp = (const ulonglong2*)(wsg + (size_t)(wid * 40) * 12);
                    #pragma unroll 4
                    for (int p = 0; p < 32; ++p) {
                        ull zA = pack2(zr[(2*p)*64],      zr[(2*p+1)*64]);
                        ull zB = pack2(zr[(2*p)*64 + 32], zr[(2*p+1)*64 + 32]);
                        ulonglong2 w0 = wp[p*6+0], w1 = wp[p*6+1], w2 = wp[p*6+2];
                        accA[0] = ffma2(zA, w0.x, accA[0]);  accB[0] = ffma2(zB, w0.x, accB[0]);
                        accA[1] = ffma2(zA, w0.y, accA[1]);  accB[1] = ffma2(zB, w0.y, accB[1]);
                        accA[2] = ffma2(zA, w1.x, accA[2]);  accB[2] = ffma2(zB, w1.x, accB[2]);
                        accA[3] = ffma2(zA, w1.y, accA[3]);  accB[3] = ffma2(zB, w1.y, accB[3]);
                        accA[4] = ffma2(zA, w2.x, accA[4]);  accB[4] = ffma2(zB, w2.x, accB[4]);
                        accA[5] = ffma2(zA, w2.y, accA[5]);  accB[5] = ffma2(zB, w2.y, accB[5]);
                        ulonglong2 w3 = wp[p*6+3], w4 = wp[p*6+4], w5 = wp[p*6+5];
                        accA[6] = ffma2(zA, w3.x, accA[6]);   accB[6]  = ffma2(zB, w3.x, accB[6]);
                        accA[7] = ffma2(zA, w3.y, accA[7]);   accB[7]  = ffma2(zB, w3.y, accB[7]);
                        accA[8] = ffma2(zA, w4.x, accA[8]);   accB[8]  = ffma2(zB, w4.x, accB[8]);
                        accA[9] = ffma2(zA, w4.y, accA[9]);   accB[9]  = ffma2(zB, w4.y, accB[9]);
                        accA[10] = ffma2(zA, w5.x, accA[10]); accB[10] = ffma2(zB, w5.x, accB[10]);
                        accA[11] = ffma2(zA, w5.y, accA[11]); accB[11] = ffma2(zB, w5.y, accB[11]);
                    }
                }
                __syncthreads();   // readers done with hsm/xsm
                #pragma unroll
                for (int j = 0; j < 12; ++j) {
                    redsm[(wid * 12 + j) * 64 + lane]      = accA[j];
                    redsm[(wid * 12 + j) * 64 + lane + 32] = accB[j];
                }
            } else {
                ull accA[16], accB[16];
                #pragma unroll
                for (int j = 0; j < 16; ++j) { accA[j] = 0ULL; accB[j] = 0ULL; }
                mbar_wait(hbar0 + (wid >> 1) * 8, hph);
                const float* zr = hsm + (wid * 64) * 64 + lane;
                const ulonglong2* wp = (const ulonglong2*)(wso + (size_t)(wid * 32) * 16);
                #pragma unroll 4
                for (int p = 0; p < 32; ++p) {
                    ull zA = pack2(zr[(2*p)*64],      zr[(2*p+1)*64]);
                    ull zB = pack2(zr[(2*p)*64 + 32], zr[(2*p+1)*64 + 32]);
                    #pragma unroll
                    for (int q = 0; q < 8; ++q) {
                        ulonglong2 w = wp[p * 8 + q];
                        accA[2*q]   = ffma2(zA, w.x, accA[2*q]);
                        accB[2*q]   = ffma2(zB, w.x, accB[2*q]);
                        accA[2*q+1] = ffma2(zA, w.y, accA[2*q+1]);
                        accB[2*q+1] = ffma2(zB, w.y, accB[2*q+1]);
                    }
                }
                __syncthreads();
                #pragma unroll
                for (int j = 0; j < 16; ++j) {
                    redsm[(wid * 16 + j) * 64 + lane]      = accA[j];
                    redsm[(wid * 16 + j) * 64 + lane + 32] = accB[j];
                }
            }
        } else {
            __syncthreads();
        }

        // Prefetch x(u+1) — overlaps reduce/elementwise/barrier.
        if (!isOut && (u + 1) < TSTEPS && tid == 0) {
            mbar_expect(xbar, 32768);
            bulk_g2s_mc(smem_u32(xsm) + rank * 8192,
                        g_xT + (size_t)(u + 1) * 8192 + rank * 2048, 8192, xbar, 0xF);
        }
        __syncthreads();

        if (active) {
            if (isOut) {
                // outputs for step u-1; thread covers 4 (col,b) cells
                #pragma unroll
                for (int q = 0; q < 4; ++q) {
                    int cix = tid + q * 256;
                    int j = cix >> 6, b = cix & 63;
                    int oc = oc0 + j;
                    float s = 0.f;
                    #pragma unroll
                    for (int w = 0; w < 8; ++w) {
                        ull v = redsm[(w * 16 + j) * 64 + b];
                        s += lo32(v) + hi32(v);
                    }
                    out[((size_t)(u - 1) * BB + b) * OO + oc] = s + b_out[oc];
                }
            } else {
                // fused reduce + elementwise for (h0+eh, eb)
                float pi = rbi, po = rbo, pc = rbc;
                #pragma unroll
                for (int w = 0; w < 8; ++w) {
                    int base = (w * 12 + eh * 3) * 64 + eb;
                    ull v0 = redsm[base];
                    ull v1 = redsm[base + 64];
                    ull v2 = redsm[base + 128];
                    pi += lo32(v0) + hi32(v0);
                    po += lo32(v1) + hi32(v1);
                    pc += lo32(v2) + hi32(v2);
                }
                float iv = sigm(pi);
                float ov = sigm(po);
                float gv = tanhf(pc);
                int h = h0 + eh;
                float l0 = 0.f, l1 = 0.f, l2 = 0.f, l3 = 0.f;
                #pragma unroll
                for (int j = 0; j < KK; j += 4) {
                    l0 += wd_sm[eh * KK + j    ] * rv[j];
                    l1 += wd_sm[eh * KK + j + 1] * rv[j + 1];
                    l2 += wd_sm[eh * KK + j + 2] * rv[j + 2];
                    l3 += wd_sm[eh * KK + j + 3] * rv[j + 3];
                }
                float cc = iv * gv - ((l0 + l1) + (l2 + l3));
                float hn = ov * tanhf(cc);
                #pragma unroll
                for (int j = 0; j < KK - 1; ++j) rv[j] = rv[j + 1];
                rv[KK - 1] = cc;
                if (u >= TSTEPS - KK)
                    g_ring[((u - (TSTEPS - KK)) << 15) + h * 64 + eb] = cc;
                g_zH[h * 64 + eb] = hn;
                if (u == TSTEPS - 1)
                    out[(size_t)TSTEPS * BB * OO + (size_t)eb * HH + h] = hn;  // h_last
                xph ^= 1;
            }
            hph ^= 1;
        }
        gridbar(barid++);
    }

    // hc_last[j][b][h]: slot j holds c_{480+j}
    const size_t OFF_HC = (size_t)TSTEPS * BB * OO + (size_t)BB * HH;
    for (int idx = gtid; idx < KK * BB * HH; idx += GT) {
        int j = idx >> 15;
        int r = idx & 32767;
        int b = r >> 9, h = r & 511;
        out[OFF_HC + idx] = __ldcg(&g_ring[((size_t)j << 15) + h * 64 + b]);
    }
}

extern "C" void kernel_launch(void* const* d_in, const int* in_sizes, int n_in,
                              void* d_out, int out_size) {
    (void)in_sizes; (void)n_in; (void)out_size;
    const float* inputs   = (const float*)d_in[0];
    const float* W_i      = (const float*)d_in[1];
    const float* b_i      = (const float*)d_in[2];
    const float* W_o      = (const float*)d_in[3];
    const float* b_o      = (const float*)d_in[4];
    const float* W_c      = (const float*)d_in[5];
    const float* b_c      = (const float*)d_in[6];
    const float* W_out    = (const float*)d_in[7];
    const float* b_out    = (const float*)d_in[8];
    const float* d_values = (const float*)d_in[9];
    float* out = (float*)d_out;

    cudaFuncSetAttribute(mlstm_kernel, cudaFuncAttributeMaxDynamicSharedMemorySize, SMEM_BYTES);
    mlstm_kernel<<<NBLK, NTH, SMEM_BYTES>>>(inputs, W_i, b_i, W_o, b_o, W_c, b_c,
                                            W_out, b_out, d_values, out);
}

// round 16
// speedup vs baseline: 1.1991x; 1.1991x over previous
#include <cuda_runtime.h>
#include <cuda_bf16.h>
#include <cstdint>

// Problem constants
#define TSTEPS 512
#define BB 64
#define II 128
#define HH 512
#define OO 128
#define KK 32
#define ZK 640                  // I + H
#define NBLK 139                // 128 gate blocks + 11 out blocks
#define NTH 256
#define GT (NBLK*NTH)

// smem layout (bytes)
#define HSM_OFF   0             // h slice [512][64] f32 = 131072
#define XSM_OFF   131072        // x slice [128][64] f32 = 32768
#define WSM_OFF   163840        // weights k-paired [320][12] ull = 30720
#define WD_OFF    194560        // frac-diff weights [4][32] f32 = 512
#define MBAR_OFF  195072        // 4 h mbars + 1 x mbar (8B each)
#define SMEM_BYTES (MBAR_OFF + 64)

typedef unsigned long long ull;

// ------------- static device scratch (no allocations) -------------
__device__ float g_xT[TSTEPS*II*BB];     // inputs transposed: [t][k][b]
__device__ float g_zH[HH*BB];            // h_{t-1}: [h][b]
__device__ float g_ring[KK*HH*BB];       // last 32 cell states: [j][h][b]
__device__ unsigned g_cnt;
__device__ volatile unsigned g_sense_v;

// ------------- helpers -------------
__device__ __forceinline__ ull ffma2(ull a, ull b, ull c) {
    ull d;
    asm("fma.rn.f32x2 %0, %1, %2, %3;" : "=l"(d) : "l"(a), "l"(b), "l"(c));
    return d;
}
__device__ __forceinline__ ull pack2(float lo, float hi) {
    ull r;
    asm("mov.b64 %0, {%1, %2};" : "=l"(r) : "f"(lo), "f"(hi));
    return r;
}
__device__ __forceinline__ float lo32(ull v) { return __uint_as_float((unsigned)v); }
__device__ __forceinline__ float hi32(ull v) { return __uint_as_float((unsigned)(v >> 32)); }
__device__ __forceinline__ float sigm(float x) { return 1.f / (1.f + __expf(-x)); }

__device__ __forceinline__ unsigned smem_u32(const void* p) {
    return (unsigned)__cvta_generic_to_shared(p);
}
__device__ __forceinline__ void mbar_init(unsigned mbar, unsigned cnt) {
    asm volatile("mbarrier.init.shared.b64 [%0], %1;" :: "r"(mbar), "r"(cnt) : "memory");
}
__device__ __forceinline__ void mbar_expect(unsigned mbar, unsigned bytes) {
    asm volatile("mbarrier.arrive.expect_tx.shared.b64 _, [%0], %1;"
                 :: "r"(mbar), "r"(bytes) : "memory");
}
__device__ __forceinline__ void bulk_g2s(unsigned dst, const void* src,
                                         unsigned bytes, unsigned mbar) {
    asm volatile("cp.async.bulk.shared::cluster.global.mbarrier::complete_tx::bytes "
                 "[%0], [%1], %2, [%3];"
                 :: "r"(dst), "l"(src), "r"(bytes), "r"(mbar) : "memory");
}
__device__ __forceinline__ void mbar_wait(unsigned mbar, unsigned parity) {
    asm volatile(
        "{\n\t"
        ".reg .pred P;\n\t"
        "WAIT_%=:\n\t"
        "mbarrier.try_wait.parity.acquire.cta.shared::cta.b64 P, [%0], %1, 0x989680;\n\t"
        "@P bra.uni DONE_%=;\n\t"
        "bra.uni WAIT_%=;\n\t"
        "DONE_%=:\n\t"
        "}" :: "r"(mbar), "r"(parity) : "memory");
}

// Champion serial sense-reversing grid barrier; arrival pipelines at the LTS
// atomic ALU. State self-restores (even call count) for graph replay.
__device__ __forceinline__ void gridbar(unsigned n) {
    __threadfence();
    __syncthreads();
    if (threadIdx.x == 0) {
        unsigned s = (~n) & 1u;
        if (atomicAdd(&g_cnt, 1u) == NBLK - 1) {
            g_cnt = 0;
            __threadfence();
            g_sense_v = s;
        } else {
            while (g_sense_v != s) __nanosleep(16);
        }
    }
    __syncthreads();
}

extern __shared__ char smem_raw[];

__global__ void __launch_bounds__(NTH, 1)
mlstm_kernel(const float* __restrict__ inputs,
             const float* __restrict__ W_i, const float* __restrict__ b_i,
             const float* __restrict__ W_o, const float* __restrict__ b_o,
             const float* __restrict__ W_c, const float* __restrict__ b_c,
             const float* __restrict__ W_out, const float* __restrict__ b_out,
             const float* __restrict__ d_values,
             float* __restrict__ out)
{
    float* hsm   = (float*)(smem_raw + HSM_OFF);    // [512][64]
    float* xsm   = (float*)(smem_raw + XSM_OFF);    // [128][64]
    ull*   wsm   = (ull*)(smem_raw + WSM_OFF);      // [320 kpairs][12], warp-major
    float* wd_sm = (float*)(smem_raw + WD_OFF);     // [4][32]
    ull*   redsm = (ull*)(smem_raw + HSM_OFF);      // reuse h region: [8][12][64] ull

    const unsigned hbar0 = smem_u32(smem_raw + MBAR_OFF);  // 4 mbars, 8B apart
    const unsigned xbar  = hbar0 + 32;

    const int tid  = threadIdx.x;
    const int blk  = blockIdx.x;
    const int gtid = blk * NTH + tid;
    const int lane = tid & 31;
    const int wid  = tid >> 5;

    const bool isOut = (blk >= 128);
    const int h0  = blk * 4;                 // gate blocks: 4 h each
    const int oc0 = (blk - 128) * 12;        // out blocks
    const int eh  = tid >> 6;                // elementwise hh (0..3)
    const int eb  = tid & 63;                // elementwise b

    // ---------------- init ----------------
    if (tid == 0) {
        for (int c = 0; c < 4; ++c) mbar_init(hbar0 + c * 8, 1);
        mbar_init(xbar, 1);
    }
    // Weights -> smem, k-PAIRED, CHUNK-INTERLEAVED: for warp w, pair index
    // p = kp - w*40:
    //   p <  32: chunk c = p/8, q = p%8 -> h row (z k) = 128 + c*128 + w*16 + 2q
    //   p >= 32: x rows k0 = w*16 + 2*(p-32)
    // so every warp consumes 8 pairs from EVERY 32KB h-chunk (arrival-order
    // pipelining: no warp's whole h-work depends on the last chunk).
    for (int idx = tid; idx < 320 * 12; idx += NTH) {
        int kp = idx / 12;
        int j  = idx - kp * 12;
        int w  = kp / 40, p = kp - w * 40;
        int k0;
        if (p < 32) {
            int c = p >> 3, q = p & 7;
            k0 = 128 + c * 128 + w * 16 + 2 * q;
        } else {
            k0 = w * 16 + 2 * (p - 32);
        }
        float wv0 = 0.f, wv1 = 0.f;
        if (!isOut) {
            int hh = j / 3, g = j - hh * 3;
            const float* W = (g == 0) ? W_i : (g == 1) ? W_o : W_c;
            wv0 = W[k0 * HH + h0 + hh];
            wv1 = W[(k0 + 1) * HH + h0 + hh];
        } else if ((oc0 + j) < OO && k0 >= II) {
            wv0 = W_out[(k0 - II) * OO + oc0 + j];
            wv1 = W_out[(k0 + 1 - II) * OO + oc0 + j];
        }
        wsm[idx] = pack2(wv0, wv1);
    }
    float rbi = 0.f, rbo = 0.f, rbc = 0.f;
    if (!isOut) {
        if (tid < 4) {
            float dv = 0.5f * sigm(d_values[h0 + tid]);
            float v = 1.f;
            for (int i = 0; i < KK; ++i) {
                v = v * ((float)i - dv) / ((float)i + 1.f);
                wd_sm[tid * KK + (KK - 1 - i)] = v;
            }
        }
        rbi = b_i[h0 + eh]; rbo = b_o[h0 + eh]; rbc = b_c[h0 + eh];
    }
    // Transpose inputs once: g_xT[t][k][b]
    for (int idx = gtid; idx < TSTEPS * II * BB; idx += GT) {
        int t = idx >> 13;
        int r = idx & 8191;
        int k = r & 127, b = r >> 7;
        g_xT[(size_t)t * 8192 + k * 64 + b] = inputs[((size_t)t * BB + b) * II + k];
    }
    for (int idx = gtid; idx < HH * BB; idx += GT) g_zH[idx] = 0.f;
    for (int idx = gtid; idx < KK * HH * BB; idx += GT) g_ring[idx] = 0.f;
    __syncthreads();
    unsigned barid = 0;
    gridbar(barid++);

    // Prefetch x(0) (gate blocks only)
    if (!isOut && tid == 0) {
        mbar_expect(xbar, 32768);
        bulk_g2s(smem_u32(xsm), g_xT, 32768, xbar);
    }

    unsigned hph = 0, xph = 0;
    float rv[KK];                 // register shift-ring: rv[j] = c_{u-32+j}
    #pragma unroll
    for (int j = 0; j < KK; ++j) rv[j] = 0.f;

    // ---------------- main scan ----------------
    for (int u = 0; u <= TSTEPS; ++u) {
        const bool active = isOut ? (u >= 1) : (u < TSTEPS);

        // h DMA: each CTA pulls all four 32KB slices itself, in consumption order.
        if (active && tid == 0) {
            #pragma unroll
            for (int c = 0; c < 4; ++c) {
                mbar_expect(hbar0 + c * 8, 32768);
                bulk_g2s(smem_u32(hsm) + c * 32768, g_zH + c * 8192, 32768, hbar0 + c * 8);
            }
        }

        ull accA[12], accB[12];     // accA: b=lane, accB: b=lane+32; halves = (k even, k odd)
        if (active) {
            #pragma unroll
            for (int j = 0; j < 12; ++j) { accA[j] = 0ULL; accB[j] = 0ULL; }
            // x part first (gate blocks): 8 k-pairs, prefetched last step.
            if (!isOut) {
                mbar_wait(xbar, xph);
                const float* zr = xsm + (wid * 16) * 64 + lane;
                const ulonglong2* wp = (const ulonglong2*)(wsm + (size_t)(wid * 40 + 32) * 12);
                #pragma unroll
                for (int p = 0; p < 8; ++p) {
                    ull zA = pack2(zr[(2*p)*64],      zr[(2*p+1)*64]);
                    ull zB = pack2(zr[(2*p)*64 + 32], zr[(2*p+1)*64 + 32]);
                    ulonglong2 w0 = wp[p*6+0], w1 = wp[p*6+1], w2 = wp[p*6+2];
                    accA[0] = ffma2(zA, w0.x, accA[0]);  accB[0] = ffma2(zB, w0.x, accB[0]);
                    accA[1] = ffma2(zA, w0.y, accA[1]);  accB[1] = ffma2(zB, w0.y, accB[1]);
                    accA[2] = ffma2(zA, w1.x, accA[2]);  accB[2] = ffma2(zB, w1.x, accB[2]);
                    accA[3] = ffma2(zA, w1.y, accA[3]);  accB[3] = ffma2(zB, w1.y, accB[3]);
                    accA[4] = ffma2(zA, w2.x, accA[4]);  accB[4] = ffma2(zB, w2.x, accB[4]);
                    accA[5] = ffma2(zA, w2.y, accA[5]);  accB[5] = ffma2(zB, w2.y, accB[5]);
                    ulonglong2 w3 = wp[p*6+3], w4 = wp[p*6+4], w5 = wp[p*6+5];
                    accA[6] = ffma2(zA, w3.x, accA[6]);   accB[6]  = ffma2(zB, w3.x, accB[6]);
                    accA[7] = ffma2(zA, w3.y, accA[7]);   accB[7]  = ffma2(zB, w3.y, accB[7]);
                    accA[8] = ffma2(zA, w4.x, accA[8]);   accB[8]  = ffma2(zB, w4.x, accB[8]);
                    accA[9] = ffma2(zA, w4.y, accA[9]);   accB[9]  = ffma2(zB, w4.y, accB[9]);
                    accA[10] = ffma2(zA, w5.x, accA[10]); accB[10] = ffma2(zB, w5.x, accB[10]);
                    accA[11] = ffma2(zA, w5.y, accA[11]); accB[11] = ffma2(zB, w5.y, accB[11]);
                }
            }
            // h part: 4 chunk segments x 8 k-pairs, consumed in ARRIVAL order.
            #pragma unroll
            for (int c = 0; c < 4; ++c) {
                mbar_wait(hbar0 + c * 8, hph);
                const float* zr = hsm + (c * 128 + wid * 16) * 64 + lane;
                const ulonglong2* wp = (const ulonglong2*)(wsm + (size_t)(wid * 40 + c * 8) * 12);
                #pragma unroll
                for (int p = 0; p < 8; ++p) {
                    ull zA = pack2(zr[(2*p)*64],      zr[(2*p+1)*64]);
                    ull zB = pack2(zr[(2*p)*64 + 32], zr[(2*p+1)*64 + 32]);
                    ulonglong2 w0 = wp[p*6+0], w1 = wp[p*6+1], w2 = wp[p*6+2];
                    accA[0] = ffma2(zA, w0.x, accA[0]);  accB[0] = ffma2(zB, w0.x, accB[0]);
                    accA[1] = ffma2(zA, w0.y, accA[1]);  accB[1] = ffma2(zB, w0.y, accB[1]);
                    accA[2] = ffma2(zA, w1.x, accA[2]);  accB[2] = ffma2(zB, w1.x, accB[2]);
                    accA[3] = ffma2(zA, w1.y, accA[3]);  accB[3] = ffma2(zB, w1.y, accB[3]);
                    accA[4] = ffma2(zA, w2.x, accA[4]);  accB[4] = ffma2(zB, w2.x, accB[4]);
                    accA[5] = ffma2(zA, w2.y, accA[5]);  accB[5] = ffma2(zB, w2.y, accB[5]);
                    ulonglong2 w3 = wp[p*6+3], w4 = wp[p*6+4], w5 = wp[p*6+5];
                    accA[6] = ffma2(zA, w3.x, accA[6]);   accB[6]  = ffma2(zB, w3.x, accB[6]);
                    accA[7] = ffma2(zA, w3.y, accA[7]);   accB[7]  = ffma2(zB, w3.y, accB[7]);
                    accA[8] = ffma2(zA, w4.x, accA[8]);   accB[8]  = ffma2(zB, w4.x, accB[8]);
                    accA[9] = ffma2(zA, w4.y, accA[9]);   accB[9]  = ffma2(zB, w4.y, accB[9]);
                    accA[10] = ffma2(zA, w5.x, accA[10]); accB[10] = ffma2(zB, w5.x, accB[10]);
                    accA[11] = ffma2(zA, w5.y, accA[11]); accB[11] = ffma2(zB, w5.y, accB[11]);
                }
            }
        }
        __syncthreads();   // all warps done reading hsm/xsm before redsm / x-prefetch

        // Prefetch x(u+1) (gate blocks) — overlaps reduce/elementwise/barrier.
        if (!isOut && (u + 1) < TSTEPS && tid == 0) {
            mbar_expect(xbar, 32768);
            bulk_g2s(smem_u32(xsm), g_xT + (size_t)(u + 1) * 8192, 32768, xbar);
        }

        if (active) {
            #pragma unroll
            for (int j = 0; j < 12; ++j) {
                redsm[(wid * 12 + j) * 64 + lane]      = accA[j];
                redsm[(wid * 12 + j) * 64 + lane + 32] = accB[j];
            }
        }
        __syncthreads();

        if (active) {
            if (isOut) {
                // outputs for step u-1; thread covers 3 (col,b) cells
                #pragma unroll
                for (int q = 0; q < 3; ++q) {
                    int cix = tid + q * 256;
                    int j = cix >> 6, b = cix & 63;
                    int oc = oc0 + j;
                    if (oc < OO) {
                        float s = 0.f;
                        #pragma unroll
                        for (int w = 0; w < 8; ++w) {
                            ull v = redsm[(w * 12 + j) * 64 + b];
                            s += lo32(v) + hi32(v);
                        }
                        out[((size_t)(u - 1) * BB + b) * OO + oc] = s + b_out[oc];
                    }
                }
            } else {
                // fused reduce + elementwise for (h0+eh, eb)
                float pi = rbi, po = rbo, pc = rbc;
                #pragma unroll
                for (int w = 0; w < 8; ++w) {
                    int base = (w * 12 + eh * 3) * 64 + eb;
                    ull v0 = redsm[base];
                    ull v1 = redsm[base + 64];
                    ull v2 = redsm[base + 128];
                    pi += lo32(v0) + hi32(v0);
                    po += lo32(v1) + hi32(v1);
                    pc += lo32(v2) + hi32(v2);
                }
                float iv = sigm(pi);
                float ov = sigm(po);
                float gv = tanhf(pc);
                int h = h0 + eh;
                // lag from register shift-ring
                float l0 = 0.f, l1 = 0.f, l2 = 0.f, l3 = 0.f;
                #pragma unroll
                for (int j = 0; j < KK; j += 4) {
                    l0 += wd_sm[eh * KK + j    ] * rv[j];
                    l1 += wd_sm[eh * KK + j + 1] * rv[j + 1];
                    l2 += wd_sm[eh * KK + j + 2] * rv[j + 2];
                    l3 += wd_sm[eh * KK + j + 3] * rv[j + 3];
                }
                float cc = iv * gv - ((l0 + l1) + (l2 + l3));
                float hn = ov * tanhf(cc);
                #pragma unroll
                for (int j = 0; j < KK - 1; ++j) rv[j] = rv[j + 1];
                rv[KK - 1] = cc;
                // gmem ring only for the last 32 steps (all hc_last needs)
                if (u >= TSTEPS - KK)
                    g_ring[((u - (TSTEPS - KK)) << 15) + h * 64 + eb] = cc;
                g_zH[h * 64 + eb] = hn;
                if (u == TSTEPS - 1)
                    out[(size_t)TSTEPS * BB * OO + (size_t)eb * HH + h] = hn;  // h_last
                xph ^= 1;
            }
            hph ^= 1;
        }
        gridbar(barid++);
    }

    // hc_last[j][b][h]: slot j holds c_{480+j}
    const size_t OFF_HC = (size_t)TSTEPS * BB * OO + (size_t)BB * HH;
    for (int idx = gtid; idx < KK * BB * HH; idx += GT) {
        int j = idx >> 15;
        int r = idx & 32767;
        int b = r >> 9, h = r & 511;
        out[OFF_HC + idx] = __ldcg(&g_ring[((size_t)j << 15) + h * 64 + b]);
    }
}

extern "C" void kernel_launch(void* const* d_in, const int* in_sizes, int n_in,
                              void* d_out, int out_size) {
    (void)in_sizes; (void)n_in; (void)out_size;
    const float* inputs   = (const float*)d_in[0];
    const float* W_i      = (const float*)d_in[1];
    const float* b_i      = (const float*)d_in[2];
    const float* W_o      = (const float*)d_in[3];
    const float* b_o      = (const float*)d_in[4];
    const float* W_c      = (const float*)d_in[5];
    const float* b_c      = (const float*)d_in[6];
    const float* W_out    = (const float*)d_in[7];
    const float* b_out    = (const float*)d_in[8];
    const float* d_values = (const float*)d_in[9];
    float* out = (float*)d_out;

    cudaFuncSetAttribute(mlstm_kernel, cudaFuncAttributeMaxDynamicSharedMemorySize, SMEM_BYTES);
    mlstm_kernel<<<NBLK, NTH, SMEM_BYTES>>>(inputs, W_i, b_i, W_o, b_o, W_c, b_c,
                                            W_out, b_out, d_values, out);
}